// round 7
// baseline (speedup 1.0000x reference)
#include <cuda_runtime.h>
#include <cuda_pipeline_primitives.h>
#include <stdint.h>

#define NUM_VERBS  117
#define NUM_HOIS   600
#define HOI_VEC    150                 // float4 per row
#define TILE_ROWS  32
#define THREADS    256                 // 8 warps; each warp -> 4 rows of a tile
#define NWARPS     8
#define NBLOCKS    512
#define TILE_F     (TILE_ROWS * NUM_VERBS)   // 3744 floats per tile
#define TILE_F4    (TILE_F / 4)              // 936 float4 per tile

__global__ __launch_bounds__(THREADS, 6)
void scatter_verbs_kernel(const float* __restrict__ verb_scores,
                          const int*   __restrict__ map_words,  // int32 OR int64 words
                          float* __restrict__ out,
                          int batch)
{
    __shared__ __align__(16) float s_vs[2][TILE_F];

    const int tid  = threadIdx.x;
    const int lane = tid & 31;
    const int wid  = tid >> 5;

    // ---- detect map dtype once: int64 little-endian => odd 32-bit words zero.
    bool is64 = true;
    #pragma unroll
    for (int j = 0; j < 8; j++)
        is64 &= (__ldg(map_words + 2 * j + 1) == 0);

    // ---- preload this lane's 20 map indices into registers (once per block)
    int idx[5][4];
    #pragma unroll
    for (int k = 0; k < 5; k++) {
        int q = lane + 32 * k;              // float4 column index
        if (q < HOI_VEC) {
            int h = 4 * q;
            if (is64) {
                idx[k][0] = __ldg(map_words + 2 * (h + 0));
                idx[k][1] = __ldg(map_words + 2 * (h + 1));
                idx[k][2] = __ldg(map_words + 2 * (h + 2));
                idx[k][3] = __ldg(map_words + 2 * (h + 3));
            } else {
                int4 m = __ldg(reinterpret_cast<const int4*>(map_words) + q);
                idx[k][0] = m.x; idx[k][1] = m.y; idx[k][2] = m.z; idx[k][3] = m.w;
            }
        }
    }

    const int total_tiles = (batch + TILE_ROWS - 1) / TILE_ROWS;   // 4096

    // ---- async staging helper (contiguous float4 copy)
    auto prefetch = [&](int tile, int buf) {
        int row0 = tile * TILE_ROWS;
        int nrow = min(TILE_ROWS, batch - row0);
        int n4   = (nrow * NUM_VERBS + 3) / 4;
        int max4 = (int)(((size_t)batch * NUM_VERBS) / 4 - (size_t)row0 * NUM_VERBS / 4);
        n4 = min(n4, max4);
        const float4* src4 = reinterpret_cast<const float4*>(
            verb_scores + (size_t)row0 * NUM_VERBS);
        float4* dst4 = reinterpret_cast<float4*>(s_vs[buf]);
        for (int i = tid; i < n4; i += THREADS)
            __pipeline_memcpy_async(dst4 + i, src4 + i, 16);
    };

    int t   = blockIdx.x;
    int buf = 0;
    if (t < total_tiles) prefetch(t, buf);
    __pipeline_commit();

    for (; t < total_tiles; t += NBLOCKS) {
        int tn = t + NBLOCKS;
        if (tn < total_tiles) prefetch(tn, buf ^ 1);
        __pipeline_commit();
        __pipeline_wait_prior(1);       // tile t's group complete
        __syncthreads();

        // ---- gather + coalesced float4 streaming stores for tile t
        const int row0 = t * TILE_ROWS;
        const int nrow = min(TILE_ROWS, batch - row0);
        float4* out4 = reinterpret_cast<float4*>(out + (size_t)row0 * NUM_HOIS);
        const float* base = s_vs[buf];

        #pragma unroll
        for (int j = 0; j < 4; j++) {
            int r = wid + NWARPS * j;
            if (r < nrow) {
                const float* vrow = base + r * NUM_VERBS;
                float4* orow = out4 + (size_t)r * HOI_VEC;
                #pragma unroll
                for (int k = 0; k < 5; k++) {
                    int q = lane + 32 * k;
                    if (q < HOI_VEC) {
                        float4 v;
                        v.x = vrow[idx[k][0]];
                        v.y = vrow[idx[k][1]];
                        v.z = vrow[idx[k][2]];
                        v.w = vrow[idx[k][3]];
                        __stcs(orow + q, v);
                    }
                }
            }
        }
        __syncthreads();                // buffer reuse safety
        buf ^= 1;
    }
}

extern "C" void kernel_launch(void* const* d_in, const int* in_sizes, int n_in,
                              void* d_out, int out_size)
{
    const float* verb_scores = (const float*)d_in[0];
    const int*   map_words   = (const int*)d_in[1];
    float*       out         = (float*)d_out;

    const int batch = in_sizes[0] / NUM_VERBS;   // 131072

    scatter_verbs_kernel<<<NBLOCKS, THREADS>>>(verb_scores, map_words, out, batch);
}

// round 9
// speedup vs baseline: 1.1291x; 1.1291x over previous
#include <cuda_runtime.h>
#include <cuda_pipeline_primitives.h>
#include <stdint.h>

#define NUM_VERBS  117
#define NUM_HOIS   600
#define HOI_VEC    150                 // float4 per row
#define TILE_ROWS  32
#define THREADS    256                 // 8 warps; each warp -> 4 rows of a tile
#define NWARPS     8
#define NBLOCKS    1024                // ~6.9/SM; smem-limited 7 resident -> ~85% occ
#define TILE_F     (TILE_ROWS * NUM_VERBS)   // 3744 floats per tile

__global__ __launch_bounds__(THREADS)
void scatter_verbs_kernel(const float* __restrict__ verb_scores,
                          const int*   __restrict__ map_words,  // int32 OR int64 words
                          float* __restrict__ out,
                          int batch)
{
    __shared__ __align__(16) float s_vs[2][TILE_F];

    const int tid  = threadIdx.x;
    const int lane = tid & 31;
    const int wid  = tid >> 5;

    // ---- detect map dtype once: int64 little-endian => odd 32-bit words zero.
    bool is64 = true;
    #pragma unroll
    for (int j = 0; j < 8; j++)
        is64 &= (__ldg(map_words + 2 * j + 1) == 0);

    // ---- preload this lane's 20 map indices into registers (once per block)
    int idx[5][4];
    #pragma unroll
    for (int k = 0; k < 5; k++) {
        int q = lane + 32 * k;              // float4 column index
        if (q < HOI_VEC) {
            int h = 4 * q;
            if (is64) {
                idx[k][0] = __ldg(map_words + 2 * (h + 0));
                idx[k][1] = __ldg(map_words + 2 * (h + 1));
                idx[k][2] = __ldg(map_words + 2 * (h + 2));
                idx[k][3] = __ldg(map_words + 2 * (h + 3));
            } else {
                int4 m = __ldg(reinterpret_cast<const int4*>(map_words) + q);
                idx[k][0] = m.x; idx[k][1] = m.y; idx[k][2] = m.z; idx[k][3] = m.w;
            }
        }
    }

    const int total_tiles = (batch + TILE_ROWS - 1) / TILE_ROWS;   // 4096

    // ---- async staging helper (contiguous float4 copy)
    auto prefetch = [&](int tile, int buf) {
        int row0 = tile * TILE_ROWS;
        int nrow = min(TILE_ROWS, batch - row0);
        int n4   = (nrow * NUM_VERBS + 3) / 4;
        int max4 = (int)(((size_t)batch * NUM_VERBS) / 4 - (size_t)row0 * NUM_VERBS / 4);
        n4 = min(n4, max4);
        const float4* src4 = reinterpret_cast<const float4*>(
            verb_scores + (size_t)row0 * NUM_VERBS);
        float4* dst4 = reinterpret_cast<float4*>(s_vs[buf]);
        for (int i = tid; i < n4; i += THREADS)
            __pipeline_memcpy_async(dst4 + i, src4 + i, 16);
    };

    int t   = blockIdx.x;
    int buf = 0;
    if (t < total_tiles) prefetch(t, buf);
    __pipeline_commit();

    for (; t < total_tiles; t += NBLOCKS) {
        int tn = t + NBLOCKS;
        if (tn < total_tiles) prefetch(tn, buf ^ 1);
        __pipeline_commit();
        __pipeline_wait_prior(1);       // tile t's group complete
        __syncthreads();

        // ---- gather + coalesced float4 streaming stores for tile t
        const int row0 = t * TILE_ROWS;
        const int nrow = min(TILE_ROWS, batch - row0);
        float4* out4 = reinterpret_cast<float4*>(out + (size_t)row0 * NUM_HOIS);
        const float* base = s_vs[buf];

        #pragma unroll
        for (int j = 0; j < 4; j++) {
            int r = wid + NWARPS * j;
            if (r < nrow) {
                const float* vrow = base + r * NUM_VERBS;
                float4* orow = out4 + (size_t)r * HOI_VEC;
                #pragma unroll
                for (int k = 0; k < 5; k++) {
                    int q = lane + 32 * k;
                    if (q < HOI_VEC) {
                        float4 v;
                        v.x = vrow[idx[k][0]];
                        v.y = vrow[idx[k][1]];
                        v.z = vrow[idx[k][2]];
                        v.w = vrow[idx[k][3]];
                        __stcs(orow + q, v);
                    }
                }
            }
        }
        __syncthreads();                // buffer reuse safety
        buf ^= 1;
    }
}

extern "C" void kernel_launch(void* const* d_in, const int* in_sizes, int n_in,
                              void* d_out, int out_size)
{
    const float* verb_scores = (const float*)d_in[0];
    const int*   map_words   = (const int*)d_in[1];
    float*       out         = (float*)d_out;

    const int batch = in_sizes[0] / NUM_VERBS;   // 131072

    scatter_verbs_kernel<<<NBLOCKS, THREADS>>>(verb_scores, map_words, out, batch);
}